// round 16
// baseline (speedup 1.0000x reference)
#include <cuda_runtime.h>
#include <cuda_fp16.h>
#include <cstdint>

// ---------------------------------------------------------------------------
// Problem constants
// ---------------------------------------------------------------------------
namespace cfg {
constexpr int Dm   = 1024;
constexpr int NH   = 16;
constexpr int DK   = 64;
constexpr int CH   = 64;
constexpr int B    = 4;
constexpr int L    = 4096;
constexpr int NC   = L / CH;   // 64
constexpr int T    = B * L;    // 16384
constexpr int QC   = 3 * Dm;   // 3072
constexpr int NT   = B * NH * NC;       // 4096 tiles
constexpr int TS   = CH * DK;           // 4096 elems / tile
}

// ---------------------------------------------------------------------------
// Static device scratch
// ---------------------------------------------------------------------------
__device__ float    g_state[(size_t)cfg::NT * cfg::TS];         // 64 MiB (G)
__device__ __half   g_act[(size_t)cfg::T * cfg::Dm];            // x / y fp16
__device__ __half   g_wq[(size_t)cfg::QC * cfg::Dm];            // W_qkv^T fp16
__device__ __half   g_wo[(size_t)cfg::Dm * cfg::Dm];            // W_o^T fp16
// chunk tiles, [b][h][c][64][64]
__device__ __half   g_qh[(size_t)cfg::NT * cfg::TS];            // q hi
__device__ __half   g_ql[(size_t)cfg::NT * cfg::TS];            // q lo
__device__ __half   g_kk[(size_t)cfg::NT * cfg::TS];            // LN(k), single
__device__ __half   g_vr[(size_t)cfg::NT * cfg::TS];            // v row-major [t][d]
__device__ __half   g_vt[(size_t)cfg::NT * cfg::TS];            // v^T [d][t]
__device__ __half   g_ss[(size_t)cfg::NT * cfg::TS];            // S, single

// ---------------------------------------------------------------------------
// PTX helpers
// ---------------------------------------------------------------------------
__device__ __forceinline__ uint32_t smem_u32(const void* p) {
    uint32_t a;
    asm("{ .reg .u64 t; cvta.to.shared.u64 t, %1; cvt.u32.u64 %0, t; }"
        : "=r"(a) : "l"(p));
    return a;
}
#define CP16(dst, src) \
    asm volatile("cp.async.cg.shared.global [%0], [%1], 16;" :: "r"(dst), "l"(src))
#define CP_COMMIT() asm volatile("cp.async.commit_group;" ::: "memory")
#define CP_WAIT(n)  asm volatile("cp.async.wait_group %0;" :: "n"(n) : "memory")

__device__ __forceinline__ void ldsm4(uint32_t* r, uint32_t addr) {
    asm volatile("ldmatrix.sync.aligned.m8n8.x4.shared.b16 {%0,%1,%2,%3}, [%4];"
                 : "=r"(r[0]), "=r"(r[1]), "=r"(r[2]), "=r"(r[3]) : "r"(addr));
}
__device__ __forceinline__ void mma16816h(float* c, const uint32_t* a, const uint32_t* b) {
    asm volatile(
        "mma.sync.aligned.m16n8k16.row.col.f32.f16.f16.f32 "
        "{%0,%1,%2,%3}, {%4,%5,%6,%7}, {%8,%9}, {%0,%1,%2,%3};"
        : "+f"(c[0]), "+f"(c[1]), "+f"(c[2]), "+f"(c[3])
        : "r"(a[0]), "r"(a[1]), "r"(a[2]), "r"(a[3]), "r"(b[0]), "r"(b[1]));
}
__device__ __forceinline__ void split2h(float x, __half& h, __half& l) {
    h = __float2half_rn(x);
    l = __float2half_rn(x - __half2float(h));
}

// ---------------------------------------------------------------------------
// GEMM mainloop shape (proven R15): CTA 128x128, 256 thr, warp 32x64,
// 3-stage cp.async (96 KiB), 2 CTAs/SM.
// ---------------------------------------------------------------------------
namespace gm {
constexpr int TILE_B  = 128 * 128;
constexpr int STAGE_B = 2 * TILE_B;         // 32 KiB (A, B)
constexpr int SMEM_SZ = 3 * STAGE_B;        // 96 KiB
}

// Mainloop macro-body: computes acc[2][8][4] for this CTA/warp.
#define GEMM_MAINLOOP(As, Bs, K)                                              \
    const __half* srcs[2] = {                                                 \
        (As) + (size_t)tm * 128 * (K), (Bs) + (size_t)tn * 128 * (K) };       \
    const int lrow = tid >> 1, lc0 = (tid & 1) * 4;                           \
    auto load_stage = [&](int chunk, int stage) {                             \
        const uint32_t st = sb + stage * gm::STAGE_B;                         \
        _Pragma("unroll")                                                     \
        for (int t2 = 0; t2 < 2; ++t2) {                                      \
            const __half* p = srcs[t2] + (size_t)lrow * (K) + chunk * 64;     \
            const uint32_t d = st + t2 * gm::TILE_B + lrow * 128;             \
            _Pragma("unroll")                                                 \
            for (int cc = 0; cc < 4; ++cc) {                                  \
                const int c = lc0 + cc;                                       \
                CP16(d + ((c ^ (lrow & 7)) * 16), p + c * 8);                 \
            }                                                                 \
        }                                                                     \
    };                                                                        \
    float acc[2][8][4];                                                       \
    _Pragma("unroll")                                                         \
    for (int t = 0; t < 2; ++t)                                               \
        _Pragma("unroll")                                                     \
        for (int j = 0; j < 8; ++j)                                           \
            _Pragma("unroll")                                                 \
            for (int r = 0; r < 4; ++r) acc[t][j][r] = 0.f;                   \
    const int NK = (K) >> 6;                                                  \
    load_stage(0, 0); CP_COMMIT();                                            \
    load_stage(1, 1); CP_COMMIT();                                            \
    for (int i = 0; i < NK; ++i) {                                            \
        CP_WAIT(1);                                                           \
        __syncthreads();                                                      \
        if (i + 2 < NK) load_stage(i + 2, (i + 2) % 3);                       \
        CP_COMMIT();                                                          \
        const uint32_t st = sb + (i % 3) * gm::STAGE_B;                       \
        const uint32_t aB = st;                                               \
        const uint32_t bB = st + gm::TILE_B;                                  \
        _Pragma("unroll")                                                     \
        for (int s = 0; s < 4; ++s) {                                         \
            uint32_t af[2][4];                                                \
            _Pragma("unroll")                                                 \
            for (int t = 0; t < 2; ++t) {                                     \
                const int row = wm * 32 + t * 16 + (lane & 15);               \
                const int c   = s * 2 + (lane >> 4);                          \
                const uint32_t off = row * 128 + ((c ^ (row & 7)) * 16);      \
                ldsm4(af[t], aB + off);                                       \
            }                                                                 \
            uint32_t bf[8][2];                                                \
            _Pragma("unroll")                                                 \
            for (int p = 0; p < 4; ++p) {                                     \
                const int row = wn * 64 + p * 16 + ((lane & 16) >> 1) + (lane & 7); \
                const int c   = s * 2 + ((lane >> 3) & 1);                    \
                const uint32_t off = row * 128 + ((c ^ (row & 7)) * 16);      \
                uint32_t r[4];                                                \
                ldsm4(r, bB + off);                                           \
                bf[2 * p][0] = r[0]; bf[2 * p][1] = r[1];                     \
                bf[2 * p + 1][0] = r[2]; bf[2 * p + 1][1] = r[3];             \
            }                                                                 \
            _Pragma("unroll")                                                 \
            for (int t = 0; t < 2; ++t)                                       \
                _Pragma("unroll")                                             \
                for (int j = 0; j < 8; ++j)                                   \
                    mma16816h(acc[t][j], af[t], bf[j]);                       \
        }                                                                     \
    }

// ---------------------------------------------------------------------------
// Plain GEMM (out projection): C fp32
// ---------------------------------------------------------------------------
__global__ __launch_bounds__(256, 2) void gemm_fp16_kernel(
    const __half* __restrict__ As, const __half* __restrict__ Bs,
    float* __restrict__ C, int N, int K)
{
    extern __shared__ char smem[];
    const uint32_t sb = smem_u32(smem);
    const int tid = threadIdx.x, wid = tid >> 5, lane = tid & 31;
    const int tn = blockIdx.x, tm = blockIdx.y;
    const int wm = wid >> 1, wn = wid & 1;

    GEMM_MAINLOOP(As, Bs, K)

    const int qr = lane >> 2, qc = (lane & 3) * 2;
#pragma unroll
    for (int t = 0; t < 2; ++t) {
        const int r0 = tm * 128 + wm * 32 + t * 16 + qr;
#pragma unroll
        for (int j = 0; j < 8; ++j) {
            const int col = tn * 128 + wn * 64 + j * 8 + qc;
            *(float2*)(C + (size_t)r0 * N + col)       = make_float2(acc[t][j][0], acc[t][j][1]);
            *(float2*)(C + (size_t)(r0 + 8) * N + col) = make_float2(acc[t][j][2], acc[t][j][3]);
        }
    }
}

// ---------------------------------------------------------------------------
// Fused qkv GEMM: epilogue writes q hi/lo tiles, LN(k) tiles, v tiles (fp16).
// Each warp's 64-col span = exactly one head in one region (q/k/v).
// ---------------------------------------------------------------------------
__global__ __launch_bounds__(256, 2) void gemm_qkv_fused_kernel(
    const __half* __restrict__ As, const __half* __restrict__ Bs,
    __half* __restrict__ qh, __half* __restrict__ ql,
    __half* __restrict__ kk, __half* __restrict__ vr, int K)
{
    using namespace cfg;
    extern __shared__ char smem[];
    const uint32_t sb = smem_u32(smem);
    const int tid = threadIdx.x, wid = tid >> 5, lane = tid & 31;
    const int tn = blockIdx.x, tm = blockIdx.y;
    const int wm = wid >> 1, wn = wid & 1;

    GEMM_MAINLOOP(As, Bs, K)

    const int qr = lane >> 2, qc = (lane & 3) * 2;
    const int colbase = tn * 128 + wn * 64;
    const int region  = colbase >> 10;            // 0=q 1=k 2=v
    const int h       = (colbase & 1023) >> 6;

#pragma unroll
    for (int t = 0; t < 2; ++t) {
#pragma unroll
        for (int half = 0; half < 2; ++half) {
            const int tok = tm * 128 + wm * 32 + t * 16 + qr + half * 8;
            const int b = tok >> 12, pos = tok & 4095;
            const int c = pos >> 6, tl = pos & 63;
            const size_t rowp =
                ((size_t)((b * NH + h) * NC + c)) * TS + (size_t)tl * 64;
            float a0[8], a1[8];
#pragma unroll
            for (int j = 0; j < 8; ++j) {
                a0[j] = acc[t][j][half * 2];
                a1[j] = acc[t][j][half * 2 + 1];
            }
            if (region == 0) {
#pragma unroll
                for (int j = 0; j < 8; ++j) {
                    __half h0, l0, h1, l1;
                    split2h(a0[j], h0, l0); split2h(a1[j], h1, l1);
                    *(__half2*)(qh + rowp + j * 8 + qc) = __halves2half2(h0, h1);
                    *(__half2*)(ql + rowp + j * 8 + qc) = __halves2half2(l0, l1);
                }
            } else if (region == 1) {
                float s = 0.f;
#pragma unroll
                for (int j = 0; j < 8; ++j) s += a0[j] + a1[j];
                s += __shfl_xor_sync(0xffffffffu, s, 1);
                s += __shfl_xor_sync(0xffffffffu, s, 2);
                const float mu = s * (1.f / 64.f);
                float q2 = 0.f;
#pragma unroll
                for (int j = 0; j < 8; ++j) {
                    const float d0 = a0[j] - mu, d1 = a1[j] - mu;
                    q2 += d0 * d0 + d1 * d1;
                }
                q2 += __shfl_xor_sync(0xffffffffu, q2, 1);
                q2 += __shfl_xor_sync(0xffffffffu, q2, 2);
                const float rstd = rsqrtf(q2 * (1.f / 64.f) + 1e-5f);
#pragma unroll
                for (int j = 0; j < 8; ++j)
                    *(__half2*)(kk + rowp + j * 8 + qc) = __halves2half2(
                        __float2half_rn((a0[j] - mu) * rstd),
                        __float2half_rn((a1[j] - mu) * rstd));
            } else {
#pragma unroll
                for (int j = 0; j < 8; ++j)
                    *(__half2*)(vr + rowp + j * 8 + qc) = __halves2half2(
                        __float2half_rn(a0[j]), __float2half_rn(a1[j]));
            }
        }
    }
}

// ---------------------------------------------------------------------------
// fp32 -> fp16 convert (x)
// ---------------------------------------------------------------------------
__global__ __launch_bounds__(256) void cvt_kernel(
    const float* __restrict__ in, __half* __restrict__ outp, int n4)
{
    const int i = blockIdx.x * 256 + threadIdx.x;
    if (i >= n4) return;
    const float4 v = *(const float4*)(in + (size_t)i * 4);
    *(__half2*)(outp + (size_t)i * 4) =
        __halves2half2(__float2half_rn(v.x), __float2half_rn(v.y));
    *(__half2*)(outp + (size_t)i * 4 + 2) =
        __halves2half2(__float2half_rn(v.z), __float2half_rn(v.w));
}

// ---------------------------------------------------------------------------
// fp32 [K][N] -> fp16 [N][K] (transpose) for weights
// ---------------------------------------------------------------------------
__global__ __launch_bounds__(256) void quantWT_kernel(
    const float* __restrict__ in, __half* __restrict__ wp, int K, int N)
{
    __shared__ float t[32][33];
    const int tx = threadIdx.x & 31, ty = threadIdx.x >> 5;
    const int n0 = blockIdx.x * 32, k0 = blockIdx.y * 32;
#pragma unroll
    for (int r = 0; r < 4; ++r)
        t[ty + 8 * r][tx] = in[(size_t)(k0 + ty + 8 * r) * N + n0 + tx];
    __syncthreads();
#pragma unroll
    for (int r = 0; r < 4; ++r) {
        const int n = n0 + ty + 8 * r, k = k0 + tx;
        wp[(size_t)n * K + k] = __float2half_rn(t[tx][ty + 8 * r]);
    }
}

// ---------------------------------------------------------------------------
// 64x64x64 fp16 MMA block ops (4 warps)
// ---------------------------------------------------------------------------
__device__ __forceinline__ void mma64_2pass(
    float acc[8][4], uint32_t aH, uint32_t aL, uint32_t bS, int wm, int lane)
{
#pragma unroll
    for (int s = 0; s < 4; ++s) {
        uint32_t ah[4], al[4];
        {
            const int arow = wm * 16 + (lane & 15);
            const int ac   = s * 2 + (lane >> 4);
            const uint32_t aoff = arow * 128 + ((ac ^ (arow & 7)) * 16);
            ldsm4(ah, aH + aoff);
            ldsm4(al, aL + aoff);
        }
        uint32_t bf[8][2];
#pragma unroll
        for (int p = 0; p < 4; ++p) {
            const int brow = p * 16 + ((lane & 16) >> 1) + (lane & 7);
            const int bc   = s * 2 + ((lane >> 3) & 1);
            const uint32_t boff = brow * 128 + ((bc ^ (brow & 7)) * 16);
            uint32_t r[4];
            ldsm4(r, bS + boff);
            bf[2 * p][0] = r[0]; bf[2 * p][1] = r[1];
            bf[2 * p + 1][0] = r[2]; bf[2 * p + 1][1] = r[3];
        }
#pragma unroll
        for (int j = 0; j < 8; ++j) {
            mma16816h(acc[j], ah, bf[j]);
            mma16816h(acc[j], al, bf[j]);
        }
    }
}

__device__ __forceinline__ void mma64_1pass(
    float acc[8][4], uint32_t aS, uint32_t bS, int wm, int lane)
{
#pragma unroll
    for (int s = 0; s < 4; ++s) {
        uint32_t af[4];
        {
            const int arow = wm * 16 + (lane & 15);
            const int ac   = s * 2 + (lane >> 4);
            const uint32_t aoff = arow * 128 + ((ac ^ (arow & 7)) * 16);
            ldsm4(af, aS + aoff);
        }
        uint32_t bf[8][2];
#pragma unroll
        for (int p = 0; p < 4; ++p) {
            const int brow = p * 16 + ((lane & 16) >> 1) + (lane & 7);
            const int bc   = s * 2 + ((lane >> 3) & 1);
            const uint32_t boff = brow * 128 + ((bc ^ (brow & 7)) * 16);
            uint32_t r[4];
            ldsm4(r, bS + boff);
            bf[2 * p][0] = r[0]; bf[2 * p][1] = r[1];
            bf[2 * p + 1][0] = r[2]; bf[2 * p + 1][1] = r[3];
        }
#pragma unroll
        for (int j = 0; j < 8; ++j)
            mma16816h(acc[j], af, bf[j]);
    }
}

// load one 64x128B fp16 tile into swizzled smem (128 threads)
__device__ __forceinline__ void cp_tile_128(
    uint32_t dst, const __half* src, int tid)
{
    const int row = tid >> 1, c0 = (tid & 1) * 4;
#pragma unroll
    for (int cc = 0; cc < 4; ++cc) {
        const int c = c0 + cc;
        CP16(dst + row * 128 + ((c ^ (row & 7)) * 16), src + row * 64 + c * 8);
    }
}

// scalar half store into swizzled 64x128B tile at (row, col)
__device__ __forceinline__ void st_sw_half(char* base, int row, int col, __half v) {
    const uint32_t off = row * 128 + ((((col >> 3) ^ (row & 7))) << 4) + (col & 7) * 2;
    *(__half*)(base + off) = v;
}

// ---------------------------------------------------------------------------
// gv: per tile — build vT (global + smem) and kT (smem), G = vT @ kT^T
// 128 threads, one (b,h,c) per block.
// ---------------------------------------------------------------------------
__global__ __launch_bounds__(128) void gv_kernel(
    const __half* __restrict__ vr, const __half* __restrict__ kk,
    __half* __restrict__ vt, float* __restrict__ G)
{
    using namespace cfg;
    __shared__ __half stg[64][66];
    __shared__ __align__(128) char sA[8192];
    __shared__ __align__(128) char sB[8192];

    const int bid = blockIdx.x, tid = threadIdx.x;
    const int wm = tid >> 5, lane = tid & 31;
    const size_t tb = (size_t)bid * TS;

    // stage v rows
    for (int i = tid; i < 2048; i += 128) {
        const int t = i >> 5, d2 = (i & 31) * 2;
        *(__half2*)&stg[t][d2] = *(const __half2*)(vr + tb + t * 64 + d2);
    }
    __syncthreads();

    // vT: write global [d][t] + swizzled smem A tile
    {
        const int d = tid >> 1, tp = (tid & 1) * 32;
#pragma unroll
        for (int tt = 0; tt < 32; tt += 2) {
            const int t = tp + tt;
            const __half v0 = stg[t][d], v1 = stg[t + 1][d];
            *(__half2*)(vt + tb + (size_t)d * 64 + t) = __halves2half2(v0, v1);
            st_sw_half(sA, d, t, v0);
            st_sw_half(sA, d, t + 1, v1);
        }
    }
    __syncthreads();

    // stage k rows
    for (int i = tid; i < 2048; i += 128) {
        const int t = i >> 5, e2 = (i & 31) * 2;
        *(__half2*)&stg[t][e2] = *(const __half2*)(kk + tb + t * 64 + e2);
    }
    __syncthreads();

    // kT into swizzled smem B tile
    {
        const int e = tid >> 1, tp = (tid & 1) * 32;
#pragma unroll
        for (int tt = 0; tt < 32; ++tt) {
            const int t = tp + tt;
            st_sw_half(sB, e, t, stg[t][e]);
        }
    }
    __syncthreads();

    // G[d][e] = sum_t v[t,d] k[t,e]
    float acc[8][4];
#pragma unroll
    for (int j = 0; j < 8; ++j)
#pragma unroll
        for (int r = 0; r < 4; ++r) acc[j][r] = 0.f;
    mma64_1pass(acc, smem_u32(sA), smem_u32(sB), wm, lane);

    const int qr = lane >> 2, qc = (lane & 3) * 2;
    float* Gp = G + tb;
#pragma unroll
    for (int j = 0; j < 8; ++j) {
        const int e = j * 8 + qc;
        *(float2*)(Gp + (wm * 16 + qr) * 64 + e)     = make_float2(acc[j][0], acc[j][1]);
        *(float2*)(Gp + (wm * 16 + qr + 8) * 64 + e) = make_float2(acc[j][2], acc[j][3]);
    }
}

// ---------------------------------------------------------------------------
// exclusive prefix over chunks, S as fp16 single
// ---------------------------------------------------------------------------
__global__ __launch_bounds__(256) void prefix_kernel(
    const float* __restrict__ G, __half* __restrict__ S)
{
    using namespace cfg;
    const int slice = blockIdx.x & 15, bh = blockIdx.x >> 4;
    const int idx = slice * 256 + threadIdx.x;
    const size_t base = (size_t)bh * NC * TS + idx;
    float run = 0.f;
    for (int c = 0; c < NC; ++c) {
        const size_t p = base + (size_t)c * TS;
        S[p] = __float2half_rn(run);
        run += G[p];
    }
}

// ---------------------------------------------------------------------------
// attention per chunk (fp16 2-pass):
//   scores = tril(q @ k^T); out = q @ S^T + scores @ vT^T -> fp16 single y
// ---------------------------------------------------------------------------
__global__ __launch_bounds__(128) void attn_mma_kernel(
    const __half* __restrict__ qh, const __half* __restrict__ ql,
    const __half* __restrict__ kk, const __half* __restrict__ Sx,
    const __half* __restrict__ vt,
    __half* __restrict__ y)
{
    using namespace cfg;
    extern __shared__ __align__(128) char sm[];
    const uint32_t sb = smem_u32(sm);
    const uint32_t sQh = sb,           sQl = sb + 8192;
    const uint32_t sK  = sb + 16384,   sS  = sb + 24576;
    const uint32_t sV  = sb + 32768;
    const uint32_t sCh = sb + 40960,   sCl = sb + 49152;

    const int bid = blockIdx.x, tid = threadIdx.x;
    const int wm = tid >> 5, lane = tid & 31;
    const int c = bid & 63, h = (bid >> 6) & 15, b = bid >> 10;
    const size_t tb = (size_t)bid * TS;

    cp_tile_128(sQh, qh + tb, tid);
    cp_tile_128(sQl, ql + tb, tid);
    cp_tile_128(sK,  kk + tb, tid);
    cp_tile_128(sS,  Sx + tb, tid);
    cp_tile_128(sV,  vt + tb, tid);
    CP_COMMIT(); CP_WAIT(0);
    __syncthreads();

    const int qr = lane >> 2, qc = (lane & 3) * 2;

    {
        float sc[8][4];
#pragma unroll
        for (int j = 0; j < 8; ++j)
#pragma unroll
            for (int r = 0; r < 4; ++r) sc[j][r] = 0.f;
        mma64_2pass(sc, sQh, sQl, sK, wm, lane);

        const int t0 = wm * 16 + qr, t1 = t0 + 8;
#pragma unroll
        for (int j = 0; j < 8; ++j) {
            const int s0 = j * 8 + qc, s1 = s0 + 1;
            if (s0 > t0) sc[j][0] = 0.f;
            if (s1 > t0) sc[j][1] = 0.f;
            if (s0 > t1) sc[j][2] = 0.f;
            if (s1 > t1) sc[j][3] = 0.f;
            __half h0, l0, h1, l1, h2, l2, h3, l3;
            split2h(sc[j][0], h0, l0); split2h(sc[j][1], h1, l1);
            split2h(sc[j][2], h2, l2); split2h(sc[j][3], h3, l3);
            const uint32_t o0 = t0 * 128 + ((j ^ (t0 & 7)) * 16) + qc * 2;
            const uint32_t o1 = t1 * 128 + ((j ^ (t1 & 7)) * 16) + qc * 2;
            *(__half2*)((char*)sm + (sCh - sb) + o0) = __halves2half2(h0, h1);
            *(__half2*)((char*)sm + (sCl - sb) + o0) = __halves2half2(l0, l1);
            *(__half2*)((char*)sm + (sCh - sb) + o1) = __halves2half2(h2, h3);
            *(__half2*)((char*)sm + (sCl - sb) + o1) = __halves2half2(l2, l3);
        }
    }
    __syncthreads();

    float acc[8][4];
#pragma unroll
    for (int j = 0; j < 8; ++j)
#pragma unroll
        for (int r = 0; r < 4; ++r) acc[j][r] = 0.f;
    mma64_2pass(acc, sQh, sQl, sS, wm, lane);
    mma64_2pass(acc, sCh, sCl, sV, wm, lane);

    const int t0 = wm * 16 + qr;
    const size_t row0 = (size_t)(b * L + c * CH + t0) * Dm + h * DK;
    const size_t row1 = row0 + (size_t)8 * Dm;
#pragma unroll
    for (int j = 0; j < 8; ++j) {
        const int d = j * 8 + qc;
        *(__half2*)(y + row0 + d) = __halves2half2(
            __float2half_rn(acc[j][0]), __float2half_rn(acc[j][1]));
        *(__half2*)(y + row1 + d) = __halves2half2(
            __float2half_rn(acc[j][2]), __float2half_rn(acc[j][3]));
    }
}

// ---------------------------------------------------------------------------
// Launcher
// ---------------------------------------------------------------------------
extern "C" void kernel_launch(void* const* d_in, const int* in_sizes, int n_in,
                              void* d_out, int out_size)
{
    using namespace cfg;
    (void)in_sizes; (void)n_in; (void)out_size;
    const float* x    = (const float*)d_in[0];
    const float* Wqkv = (const float*)d_in[1];
    const float* Wo   = (const float*)d_in[2];
    float* out = (float*)d_out;

    float* st_p;
    __half *act, *wq, *wo, *pqh, *pql, *pkk, *pvr, *pvt, *pss;
    cudaGetSymbolAddress((void**)&st_p, g_state);
    cudaGetSymbolAddress((void**)&act, g_act);
    cudaGetSymbolAddress((void**)&wq, g_wq);
    cudaGetSymbolAddress((void**)&wo, g_wo);
    cudaGetSymbolAddress((void**)&pqh, g_qh);
    cudaGetSymbolAddress((void**)&pql, g_ql);
    cudaGetSymbolAddress((void**)&pkk, g_kk);
    cudaGetSymbolAddress((void**)&pvr, g_vr);
    cudaGetSymbolAddress((void**)&pvt, g_vt);
    cudaGetSymbolAddress((void**)&pss, g_ss);

    static int attr_set = 0;
    if (!attr_set) {
        cudaFuncSetAttribute(gemm_fp16_kernel,
                             cudaFuncAttributeMaxDynamicSharedMemorySize, gm::SMEM_SZ);
        cudaFuncSetAttribute(gemm_qkv_fused_kernel,
                             cudaFuncAttributeMaxDynamicSharedMemorySize, gm::SMEM_SZ);
        cudaFuncSetAttribute(attn_mma_kernel,
                             cudaFuncAttributeMaxDynamicSharedMemorySize, 57344);
        attr_set = 1;
    }

    const int n4x = T * Dm / 4;
    cvt_kernel<<<(n4x + 255) / 256, 256>>>(x, act, n4x);
    quantWT_kernel<<<dim3(QC / 32, Dm / 32), 256>>>(Wqkv, wq, Dm, QC);
    quantWT_kernel<<<dim3(Dm / 32, Dm / 32), 256>>>(Wo, wo, Dm, Dm);

    // qkv GEMM with fused q/LN(k)/v epilogue (no fp32 qkv intermediate)
    gemm_qkv_fused_kernel<<<dim3(QC / 128, T / 128), 256, gm::SMEM_SZ>>>(
        act, wq, pqh, pql, pkk, pvr, Dm);

    // vT + G, prefix, attention
    gv_kernel<<<NT, 128>>>(pvr, pkk, pvt, st_p);
    prefix_kernel<<<B * NH * 16, 256>>>(st_p, pss);
    attn_mma_kernel<<<NT, 128, 57344>>>(pqh, pql, pkk, pss, pvt, act);

    // out = y @ W_o
    gemm_fp16_kernel<<<dim3(Dm / 128, T / 128), 256, gm::SMEM_SZ>>>(
        act, wo, out, Dm, Dm);
}

// round 17
// speedup vs baseline: 1.0290x; 1.0290x over previous
#include <cuda_runtime.h>
#include <cuda_fp16.h>
#include <cstdint>

// ---------------------------------------------------------------------------
// Problem constants
// ---------------------------------------------------------------------------
namespace cfg {
constexpr int Dm   = 1024;
constexpr int NH   = 16;
constexpr int DK   = 64;
constexpr int CH   = 64;
constexpr int B    = 4;
constexpr int L    = 4096;
constexpr int NC   = L / CH;   // 64
constexpr int T    = B * L;    // 16384
constexpr int QC   = 3 * Dm;   // 3072
constexpr int NT   = B * NH * NC;       // 4096 tiles
constexpr int TS   = CH * DK;           // 4096 elems / tile
}

// ---------------------------------------------------------------------------
// Static device scratch
// ---------------------------------------------------------------------------
__device__ float    g_qkv[(size_t)cfg::T * cfg::QC];            // 192 MiB
__device__ float    g_state[(size_t)cfg::NT * cfg::TS];         // 64 MiB (G)
__device__ __half   g_act[(size_t)cfg::T * cfg::Dm];            // x / y single fp16
__device__ __half   g_wq[(size_t)cfg::QC * cfg::Dm];            // W_qkv^T fp16
__device__ __half   g_wo[(size_t)cfg::Dm * cfg::Dm];            // W_o^T fp16
// chunk tiles, [b][h][c][64][64]
__device__ __half   g_qq[(size_t)cfg::NT * cfg::TS];            // q single
__device__ __half   g_kk[(size_t)cfg::NT * cfg::TS];            // LN(k), single
__device__ __half   g_vt[(size_t)cfg::NT * cfg::TS];            // v^T, single
__device__ __half   g_ss[(size_t)cfg::NT * cfg::TS];            // S, single

// ---------------------------------------------------------------------------
// PTX helpers
// ---------------------------------------------------------------------------
__device__ __forceinline__ uint32_t smem_u32(const void* p) {
    uint32_t a;
    asm("{ .reg .u64 t; cvta.to.shared.u64 t, %1; cvt.u32.u64 %0, t; }"
        : "=r"(a) : "l"(p));
    return a;
}
#define CP16(dst, src) \
    asm volatile("cp.async.cg.shared.global [%0], [%1], 16;" :: "r"(dst), "l"(src))
#define CP_COMMIT() asm volatile("cp.async.commit_group;" ::: "memory")
#define CP_WAIT(n)  asm volatile("cp.async.wait_group %0;" :: "n"(n) : "memory")

__device__ __forceinline__ void ldsm4(uint32_t* r, uint32_t addr) {
    asm volatile("ldmatrix.sync.aligned.m8n8.x4.shared.b16 {%0,%1,%2,%3}, [%4];"
                 : "=r"(r[0]), "=r"(r[1]), "=r"(r[2]), "=r"(r[3]) : "r"(addr));
}
__device__ __forceinline__ void mma16816h(float* c, const uint32_t* a, const uint32_t* b) {
    asm volatile(
        "mma.sync.aligned.m16n8k16.row.col.f32.f16.f16.f32 "
        "{%0,%1,%2,%3}, {%4,%5,%6,%7}, {%8,%9}, {%0,%1,%2,%3};"
        : "+f"(c[0]), "+f"(c[1]), "+f"(c[2]), "+f"(c[3])
        : "r"(a[0]), "r"(a[1]), "r"(a[2]), "r"(a[3]), "r"(b[0]), "r"(b[1]));
}
__device__ __forceinline__ void split2h(float x, __half& h, __half& l) {
    h = __float2half_rn(x);
    l = __float2half_rn(x - __half2float(h));
}

// ---------------------------------------------------------------------------
// fp16 single-pass GEMM (proven R15 shape): CTA 128x128, 256 thr,
// warp grid 4(M)x2(N), warp tile 32x64, 3-stage cp.async, 2 CTAs/SM.
// ---------------------------------------------------------------------------
namespace gm {
constexpr int TILE_B  = 128 * 128;
constexpr int STAGE_B = 2 * TILE_B;         // 32 KiB (A, B)
constexpr int SMEM_SZ = 3 * STAGE_B;        // 96 KiB
}

__global__ __launch_bounds__(256, 2) void gemm_fp16_kernel(
    const __half* __restrict__ As, const __half* __restrict__ Bs,
    float* __restrict__ C, int N, int K)
{
    extern __shared__ char smem[];
    const uint32_t sb = smem_u32(smem);
    const int tid = threadIdx.x, wid = tid >> 5, lane = tid & 31;
    const int tn = blockIdx.x, tm = blockIdx.y;
    const int wm = wid >> 1;   // 0..3 : 32-row slab
    const int wn = wid & 1;    // 0..1 : 64-col slab

    const __half* srcs[2] = {
        As + (size_t)tm * 128 * K, Bs + (size_t)tn * 128 * K };

    const int lrow = tid >> 1, lc0 = (tid & 1) * 4;

    auto load_stage = [&](int chunk, int stage) {
        const uint32_t st = sb + stage * gm::STAGE_B;
#pragma unroll
        for (int t2 = 0; t2 < 2; ++t2) {
            const __half* p = srcs[t2] + (size_t)lrow * K + chunk * 64;
            const uint32_t d = st + t2 * gm::TILE_B + lrow * 128;
#pragma unroll
            for (int cc = 0; cc < 4; ++cc) {
                const int c = lc0 + cc;
                CP16(d + ((c ^ (lrow & 7)) * 16), p + c * 8);
            }
        }
    };

    float acc[2][8][4];
#pragma unroll
    for (int t = 0; t < 2; ++t)
#pragma unroll
        for (int j = 0; j < 8; ++j)
#pragma unroll
            for (int r = 0; r < 4; ++r) acc[t][j][r] = 0.f;

    const int NK = K >> 6;
    load_stage(0, 0); CP_COMMIT();
    load_stage(1, 1); CP_COMMIT();

    for (int i = 0; i < NK; ++i) {
        CP_WAIT(1);
        __syncthreads();
        if (i + 2 < NK) load_stage(i + 2, (i + 2) % 3);
        CP_COMMIT();

        const uint32_t st = sb + (i % 3) * gm::STAGE_B;
        const uint32_t aB = st;
        const uint32_t bB = st + gm::TILE_B;

#pragma unroll
        for (int s = 0; s < 4; ++s) {
            uint32_t af[2][4];
#pragma unroll
            for (int t = 0; t < 2; ++t) {
                const int row = wm * 32 + t * 16 + (lane & 15);
                const int c   = s * 2 + (lane >> 4);
                const uint32_t off = row * 128 + ((c ^ (row & 7)) * 16);
                ldsm4(af[t], aB + off);
            }
            uint32_t bf[8][2];
#pragma unroll
            for (int p = 0; p < 4; ++p) {
                const int row = wn * 64 + p * 16 + ((lane & 16) >> 1) + (lane & 7);
                const int c   = s * 2 + ((lane >> 3) & 1);
                const uint32_t off = row * 128 + ((c ^ (row & 7)) * 16);
                uint32_t r[4];
                ldsm4(r, bB + off);
                bf[2 * p][0] = r[0]; bf[2 * p][1] = r[1];
                bf[2 * p + 1][0] = r[2]; bf[2 * p + 1][1] = r[3];
            }
#pragma unroll
            for (int t = 0; t < 2; ++t)
#pragma unroll
                for (int j = 0; j < 8; ++j)
                    mma16816h(acc[t][j], af[t], bf[j]);
        }
    }

    const int qr = lane >> 2, qc = (lane & 3) * 2;
#pragma unroll
    for (int t = 0; t < 2; ++t) {
        const int r0 = tm * 128 + wm * 32 + t * 16 + qr;
#pragma unroll
        for (int j = 0; j < 8; ++j) {
            const int col = tn * 128 + wn * 64 + j * 8 + qc;
            *(float2*)(C + (size_t)r0 * N + col)       = make_float2(acc[t][j][0], acc[t][j][1]);
            *(float2*)(C + (size_t)(r0 + 8) * N + col) = make_float2(acc[t][j][2], acc[t][j][3]);
        }
    }
}

// ---------------------------------------------------------------------------
// fp32 -> fp16 convert (activations)
// ---------------------------------------------------------------------------
__global__ __launch_bounds__(256) void cvt_kernel(
    const float* __restrict__ in, __half* __restrict__ outp, int n4)
{
    const int i = blockIdx.x * 256 + threadIdx.x;
    if (i >= n4) return;
    const float4 v = *(const float4*)(in + (size_t)i * 4);
    *(__half2*)(outp + (size_t)i * 4) =
        __halves2half2(__float2half_rn(v.x), __float2half_rn(v.y));
    *(__half2*)(outp + (size_t)i * 4 + 2) =
        __halves2half2(__float2half_rn(v.z), __float2half_rn(v.w));
}

// ---------------------------------------------------------------------------
// fp32 [K][N] -> fp16 [N][K] (transpose) for weights
// ---------------------------------------------------------------------------
__global__ __launch_bounds__(256) void quantWT_kernel(
    const float* __restrict__ in, __half* __restrict__ wp, int K, int N)
{
    __shared__ float t[32][33];
    const int tx = threadIdx.x & 31, ty = threadIdx.x >> 5;
    const int n0 = blockIdx.x * 32, k0 = blockIdx.y * 32;
#pragma unroll
    for (int r = 0; r < 4; ++r)
        t[ty + 8 * r][tx] = in[(size_t)(k0 + ty + 8 * r) * N + n0 + tx];
    __syncthreads();
#pragma unroll
    for (int r = 0; r < 4; ++r) {
        const int n = n0 + ty + 8 * r, k = k0 + tx;
        wp[(size_t)n * K + k] = __float2half_rn(t[tx][ty + 8 * r]);
    }
}

// ---------------------------------------------------------------------------
// 64x64x64 fp16 MMA block ops (4 warps)
// ---------------------------------------------------------------------------
__device__ __forceinline__ void mma64_2pass(
    float acc[8][4], uint32_t aH, uint32_t aL, uint32_t bS, int wm, int lane)
{
#pragma unroll
    for (int s = 0; s < 4; ++s) {
        uint32_t ah[4], al[4];
        {
            const int arow = wm * 16 + (lane & 15);
            const int ac   = s * 2 + (lane >> 4);
            const uint32_t aoff = arow * 128 + ((ac ^ (arow & 7)) * 16);
            ldsm4(ah, aH + aoff);
            ldsm4(al, aL + aoff);
        }
        uint32_t bf[8][2];
#pragma unroll
        for (int p = 0; p < 4; ++p) {
            const int brow = p * 16 + ((lane & 16) >> 1) + (lane & 7);
            const int bc   = s * 2 + ((lane >> 3) & 1);
            const uint32_t boff = brow * 128 + ((bc ^ (brow & 7)) * 16);
            uint32_t r[4];
            ldsm4(r, bS + boff);
            bf[2 * p][0] = r[0]; bf[2 * p][1] = r[1];
            bf[2 * p + 1][0] = r[2]; bf[2 * p + 1][1] = r[3];
        }
#pragma unroll
        for (int j = 0; j < 8; ++j) {
            mma16816h(acc[j], ah, bf[j]);
            mma16816h(acc[j], al, bf[j]);
        }
    }
}

__device__ __forceinline__ void mma64_1pass(
    float acc[8][4], uint32_t aS, uint32_t bS, int wm, int lane)
{
#pragma unroll
    for (int s = 0; s < 4; ++s) {
        uint32_t af[4];
        {
            const int arow = wm * 16 + (lane & 15);
            const int ac   = s * 2 + (lane >> 4);
            const uint32_t aoff = arow * 128 + ((ac ^ (arow & 7)) * 16);
            ldsm4(af, aS + aoff);
        }
        uint32_t bf[8][2];
#pragma unroll
        for (int p = 0; p < 4; ++p) {
            const int brow = p * 16 + ((lane & 16) >> 1) + (lane & 7);
            const int bc   = s * 2 + ((lane >> 3) & 1);
            const uint32_t boff = brow * 128 + ((bc ^ (brow & 7)) * 16);
            uint32_t r[4];
            ldsm4(r, bS + boff);
            bf[2 * p][0] = r[0]; bf[2 * p][1] = r[1];
            bf[2 * p + 1][0] = r[2]; bf[2 * p + 1][1] = r[3];
        }
#pragma unroll
        for (int j = 0; j < 8; ++j)
            mma16816h(acc[j], af, bf[j]);
    }
}

// load one 64x128B fp16 tile into swizzled smem (128 threads)
__device__ __forceinline__ void cp_tile_128(
    uint32_t dst, const __half* src, int tid)
{
    const int row = tid >> 1, c0 = (tid & 1) * 4;
#pragma unroll
    for (int cc = 0; cc < 4; ++cc) {
        const int c = c0 + cc;
        CP16(dst + row * 128 + ((c ^ (row & 7)) * 16), src + row * 64 + c * 8);
    }
}

// scalar half store into swizzled 64x128B tile at (row, col)
__device__ __forceinline__ void st_sw_half(char* base, int row, int col, __half v) {
    const uint32_t off = row * 128 + ((((col >> 3) ^ (row & 7))) << 4) + (col & 7) * 2;
    *(__half*)(base + off) = v;
}

// ---------------------------------------------------------------------------
// postproc (fused): q single, LN(k), vT, G = vT @ kT^T — one (b,h,c) per block
// ---------------------------------------------------------------------------
__global__ __launch_bounds__(128) void postproc_kernel(
    const float* __restrict__ qkv,
    __half* __restrict__ qq,
    __half* __restrict__ kk, __half* __restrict__ vt,
    float* __restrict__ G)
{
    using namespace cfg;
    __shared__ float tile[64][65];
    __shared__ __align__(128) char sKT[8192];
    __shared__ __align__(128) char sVH[8192];
    __shared__ __align__(128) char sVL[8192];

    const int bid = blockIdx.x;
    const int c = bid & 63, h = (bid >> 6) & 15, b = bid >> 10;
    const int tid = threadIdx.x, wid = tid >> 5, lane = tid & 31;
    const size_t tb = (size_t)bid * TS;
    const float* base = qkv + (size_t)(b * L + c * CH) * QC + h * DK;

    // ---- q: single fp16 ----
#pragma unroll
    for (int it = 0; it < 16; ++it) {
        const int r = wid * 16 + it;
        const float2 v = *(const float2*)(base + (size_t)r * QC + lane * 2);
        *(__half2*)(qq + tb + r * 64 + lane * 2) = __halves2half2(
            __float2half_rn(v.x), __float2half_rn(v.y));
    }

    // ---- k: LN per row -> global k (single) + smem kT ----
#pragma unroll
    for (int it = 0; it < 16; ++it) {
        const int r = wid * 16 + it;
        const float2 v = *(const float2*)(base + (size_t)r * QC + Dm + lane * 2);
        float s = v.x + v.y;
#pragma unroll
        for (int o = 16; o > 0; o >>= 1) s += __shfl_xor_sync(0xffffffffu, s, o);
        const float mu = s * (1.f / 64.f);
        const float d0 = v.x - mu, d1 = v.y - mu;
        float q2 = d0 * d0 + d1 * d1;
#pragma unroll
        for (int o = 16; o > 0; o >>= 1) q2 += __shfl_xor_sync(0xffffffffu, q2, o);
        const float rstd = rsqrtf(q2 * (1.f / 64.f) + 1e-5f);
        const __half n0 = __float2half_rn(d0 * rstd);
        const __half n1 = __float2half_rn(d1 * rstd);
        *(__half2*)(kk + tb + r * 64 + lane * 2) = __halves2half2(n0, n1);
        st_sw_half(sKT, lane * 2,     r, n0);
        st_sw_half(sKT, lane * 2 + 1, r, n1);
    }

    // ---- v into fp32 smem tile ----
    for (int i = tid; i < TS; i += 128)
        tile[i >> 6][i & 63] = base[(size_t)(i >> 6) * QC + 2 * Dm + (i & 63)];
    __syncthreads();

    // ---- vT[d][t]: global single + smem hi/lo ----
#pragma unroll
    for (int it = 0; it < 16; ++it) {
        const int d = wid * 16 + it;
        const float x0 = tile[lane * 2][d], x1 = tile[lane * 2 + 1][d];
        __half h0, l0, h1, l1;
        split2h(x0, h0, l0); split2h(x1, h1, l1);
        *(__half2*)(vt + tb + d * 64 + lane * 2) = __halves2half2(h0, h1);
        const uint32_t off = d * 128 + ((((lane >> 2) ^ (d & 7))) << 4) + (lane & 3) * 4;
        *(__half2*)(sVH + off) = __halves2half2(h0, h1);
        *(__half2*)(sVL + off) = __halves2half2(l0, l1);
    }
    __syncthreads();

    // ---- G = vT(hi/lo) @ kT^T(single) ----
    float acc[8][4];
#pragma unroll
    for (int j = 0; j < 8; ++j)
#pragma unroll
        for (int r = 0; r < 4; ++r) acc[j][r] = 0.f;
    mma64_2pass(acc, smem_u32(sVH), smem_u32(sVL), smem_u32(sKT), wid, lane);

    const int qr = lane >> 2, qc = (lane & 3) * 2;
    float* Gp = G + tb;
#pragma unroll
    for (int j = 0; j < 8; ++j) {
        const int e = j * 8 + qc;
        *(float2*)(Gp + (wid * 16 + qr) * 64 + e)     = make_float2(acc[j][0], acc[j][1]);
        *(float2*)(Gp + (wid * 16 + qr + 8) * 64 + e) = make_float2(acc[j][2], acc[j][3]);
    }
}

// ---------------------------------------------------------------------------
// exclusive prefix over chunks, S as fp16 single
// ---------------------------------------------------------------------------
__global__ __launch_bounds__(256) void prefix_kernel(
    const float* __restrict__ G, __half* __restrict__ S)
{
    using namespace cfg;
    const int slice = blockIdx.x & 15, bh = blockIdx.x >> 4;
    const int idx = slice * 256 + threadIdx.x;
    const size_t base = (size_t)bh * NC * TS + idx;
    float run = 0.f;
    for (int c = 0; c < NC; ++c) {
        const size_t p = base + (size_t)c * TS;
        S[p] = __float2half_rn(run);
        run += G[p];
    }
}

// ---------------------------------------------------------------------------
// attention per chunk:
//   scores = tril(q @ k^T)  [1-pass]; out = q @ S^T [1-pass]
//                                   + scores(hi/lo) @ vT^T [2-pass]
//   -> y fp16 single. smem: q,k,S,vT,sch,scl = 6 x 8 KiB = 48 KiB
// ---------------------------------------------------------------------------
__global__ __launch_bounds__(128) void attn_mma_kernel(
    const __half* __restrict__ qq,
    const __half* __restrict__ kk, const __half* __restrict__ Sx,
    const __half* __restrict__ vt,
    __half* __restrict__ y)
{
    using namespace cfg;
    extern __shared__ __align__(128) char sm[];
    const uint32_t sb = smem_u32(sm);
    const uint32_t sQ  = sb,           sK  = sb + 8192;
    const uint32_t sS  = sb + 16384,   sV  = sb + 24576;
    const uint32_t sCh = sb + 32768,   sCl = sb + 40960;

    const int bid = blockIdx.x, tid = threadIdx.x;
    const int wm = tid >> 5, lane = tid & 31;
    const int c = bid & 63, h = (bid >> 6) & 15, b = bid >> 10;
    const size_t tb = (size_t)bid * TS;

    cp_tile_128(sQ, qq + tb, tid);
    cp_tile_128(sK, kk + tb, tid);
    cp_tile_128(sS, Sx + tb, tid);
    cp_tile_128(sV, vt + tb, tid);
    CP_COMMIT(); CP_WAIT(0);
    __syncthreads();

    const int qr = lane >> 2, qc = (lane & 3) * 2;

    // scores = tril(q @ k^T), hi/lo to smem
    {
        float sc[8][4];
#pragma unroll
        for (int j = 0; j < 8; ++j)
#pragma unroll
            for (int r = 0; r < 4; ++r) sc[j][r] = 0.f;
        mma64_1pass(sc, sQ, sK, wm, lane);

        const int t0 = wm * 16 + qr, t1 = t0 + 8;
#pragma unroll
        for (int j = 0; j < 8; ++j) {
            const int s0 = j * 8 + qc, s1 = s0 + 1;
            if (s0 > t0) sc[j][0] = 0.f;
            if (s1 > t0) sc[j][1] = 0.f;
            if (s0 > t1) sc[j][2] = 0.f;
            if (s1 > t1) sc[j][3] = 0.f;
            __half h0, l0, h1, l1, h2, l2, h3, l3;
            split2h(sc[j][0], h0, l0); split2h(sc[j][1], h1, l1);
            split2h(sc[j][2], h2, l2); split2h(sc[j][3], h3, l3);
            const uint32_t o0 = t0 * 128 + ((j ^ (t0 & 7)) * 16) + qc * 2;
            const uint32_t o1 = t1 * 128 + ((j ^ (t1 & 7)) * 16) + qc * 2;
            *(__half2*)((char*)sm + (sCh - sb) + o0) = __halves2half2(h0, h1);
            *(__half2*)((char*)sm + (sCl - sb) + o0) = __halves2half2(l0, l1);
            *(__half2*)((char*)sm + (sCh - sb) + o1) = __halves2half2(h2, h3);
            *(__half2*)((char*)sm + (sCl - sb) + o1) = __halves2half2(l2, l3);
        }
    }
    __syncthreads();

    float acc[8][4];
#pragma unroll
    for (int j = 0; j < 8; ++j)
#pragma unroll
        for (int r = 0; r < 4; ++r) acc[j][r] = 0.f;
    mma64_1pass(acc, sQ, sS, wm, lane);          // inter = q @ S^T
    mma64_2pass(acc, sCh, sCl, sV, wm, lane);    // intra = scores @ vT^T

    const int t0 = wm * 16 + qr;
    const size_t row0 = (size_t)(b * L + c * CH + t0) * Dm + h * DK;
    const size_t row1 = row0 + (size_t)8 * Dm;
#pragma unroll
    for (int j = 0; j < 8; ++j) {
        const int d = j * 8 + qc;
        *(__half2*)(y + row0 + d) = __halves2half2(
            __float2half_rn(acc[j][0]), __float2half_rn(acc[j][1]));
        *(__half2*)(y + row1 + d) = __halves2half2(
            __float2half_rn(acc[j][2]), __float2half_rn(acc[j][3]));
    }
}

// ---------------------------------------------------------------------------
// Launcher
// ---------------------------------------------------------------------------
extern "C" void kernel_launch(void* const* d_in, const int* in_sizes, int n_in,
                              void* d_out, int out_size)
{
    using namespace cfg;
    (void)in_sizes; (void)n_in; (void)out_size;
    const float* x    = (const float*)d_in[0];
    const float* Wqkv = (const float*)d_in[1];
    const float* Wo   = (const float*)d_in[2];
    float* out = (float*)d_out;

    float *qkv_p, *st_p;
    __half *act, *wq, *wo, *pqq, *pkk, *pvt, *pss;
    cudaGetSymbolAddress((void**)&qkv_p, g_qkv);
    cudaGetSymbolAddress((void**)&st_p,  g_state);
    cudaGetSymbolAddress((void**)&act, g_act);
    cudaGetSymbolAddress((void**)&wq, g_wq);
    cudaGetSymbolAddress((void**)&wo, g_wo);
    cudaGetSymbolAddress((void**)&pqq, g_qq);
    cudaGetSymbolAddress((void**)&pkk, g_kk);
    cudaGetSymbolAddress((void**)&pvt, g_vt);
    cudaGetSymbolAddress((void**)&pss, g_ss);

    static int attr_set = 0;
    if (!attr_set) {
        cudaFuncSetAttribute(gemm_fp16_kernel,
                             cudaFuncAttributeMaxDynamicSharedMemorySize, gm::SMEM_SZ);
        cudaFuncSetAttribute(attn_mma_kernel,
                             cudaFuncAttributeMaxDynamicSharedMemorySize, 49152);
        attr_set = 1;
    }

    const int n4x = T * Dm / 4;
    cvt_kernel<<<(n4x + 255) / 256, 256>>>(x, act, n4x);
    quantWT_kernel<<<dim3(QC / 32, Dm / 32), 256>>>(Wqkv, wq, Dm, QC);
    quantWT_kernel<<<dim3(Dm / 32, Dm / 32), 256>>>(Wo, wo, Dm, Dm);

    // qkv = x @ W_qkv  (fp16 single-pass, R15 GEMM)
    gemm_fp16_kernel<<<dim3(QC / 128, T / 128), 256, gm::SMEM_SZ>>>(
        act, wq, qkv_p, QC, Dm);

    // chunk pipeline: fused postproc (q single), prefix, attention
    postproc_kernel<<<NT, 128>>>(qkv_p, pqq, pkk, pvt, st_p);
    prefix_kernel<<<B * NH * 16, 256>>>(st_p, pss);
    attn_mma_kernel<<<NT, 128, 49152>>>(pqq, pkk, pss, pvt, act);

    // out = y @ W_o
    gemm_fp16_kernel<<<dim3(Dm / 128, T / 128), 256, gm::SMEM_SZ>>>(
        act, wo, out, Dm, Dm);
}